// round 14
// baseline (speedup 1.0000x reference)
#include <cuda_runtime.h>
#include <cuda_bf16.h>
#include <cstdint>

// BCE-with-logits mean over 8192x8192, single kernel. FINAL.
// Best-evidenced plateau variant (R8): block-level dynamic scheduling,
//  - bulk: 1024-float4 chunks (measured sweet spot)
//  - tail: 256-float4 fine chunks (finish-line spread ~0.7us)
//  - static first chunk (no startup atomic storm)
// Double-buffered chunk index -> one barrier per chunk. Last-block-done
// reduction; counters self-reset (graph-replay safe).
// Measured: ncu 79.87us, DRAM 85.4% (6.77 TB/s) -- dual-stream HBM plateau.

#define NBLOCKS      1184        // 148 SMs * 8 CTAs (one full wave)
#define NTHREADS     256
#define BIG_IT       4
#define BIG_CHUNK    (NTHREADS * BIG_IT)   // 1024 float4
#define SMALL_CHUNK  NTHREADS              // 256 float4
#define SMALL_CHUNKS 2368                  // 2 * NBLOCKS fine chunks at the end

__device__ float g_partials[NBLOCKS];
__device__ unsigned int g_count = 0;    // always 0 at kernel entry
__device__ unsigned int g_work  = 0;    // always 0 at kernel entry

__device__ __forceinline__ float block_reduce(float acc, float* warp_sums)
{
    #pragma unroll
    for (int off = 16; off > 0; off >>= 1)
        acc += __shfl_down_sync(0xFFFFFFFFu, acc, off);
    int lane = threadIdx.x & 31;
    int wid  = threadIdx.x >> 5;
    if (lane == 0) warp_sums[wid] = acc;
    __syncthreads();
    float v = 0.0f;
    if (wid == 0) {
        v = (lane < NTHREADS / 32) ? warp_sums[lane] : 0.0f;
        #pragma unroll
        for (int off = 16; off > 0; off >>= 1)
            v += __shfl_down_sync(0xFFFFFFFFu, v, off);
    }
    return v;   // valid in warp 0 lane 0
}

__device__ __forceinline__ float bce1(float x, int t)
{
    // t in {0,1}: y = t ? -x : x via sign-bit XOR
    float y = __int_as_float(__float_as_int(x) ^ (t << 31));
    return fmaxf(y, 0.0f) + __logf(1.0f + __expf(-fabsf(y)));
}

__device__ __forceinline__ float bce4(float4 xv, int4 tv)
{
    float s0 = bce1(xv.x, tv.x);
    float s1 = bce1(xv.y, tv.y);
    float s2 = bce1(xv.z, tv.z);
    float s3 = bce1(xv.w, tv.w);
    return (s0 + s1) + (s2 + s3);
}

__global__ __launch_bounds__(NTHREADS) void bce_final8_kernel(
    const float* __restrict__ x, const int* __restrict__ t,
    float* __restrict__ out, long long n4, float inv_n,
    int nbig, int nchunks, long long small_base)
{
    const float4* __restrict__ x4 = (const float4*)x;
    const int4*   __restrict__ t4 = (const int4*)t;

    __shared__ int   s_chunk[2];
    __shared__ float warp_sums[NTHREADS / 32];

    float acc = 0.0f;

    // First chunk is static: no atomic on the startup critical path.
    int parity = 0;
    int chunk  = blockIdx.x;

    while (chunk < nchunks) {
        // prefetch next chunk index into the other slot (hidden under work)
        if (threadIdx.x == 0)
            s_chunk[parity ^ 1] = NBLOCKS + (int)atomicAdd(&g_work, 1u);

        long long base;
        int iters;
        if (chunk < nbig) {
            base  = (long long)chunk * BIG_CHUNK;
            iters = BIG_IT;
        } else {
            base  = small_base + (long long)(chunk - nbig) * SMALL_CHUNK;
            iters = 1;
        }
        base += threadIdx.x;

        #pragma unroll 1
        for (int j = 0; j < iters; j++) {
            long long i = base + (long long)j * NTHREADS;
            float4 xv = __ldcs(&x4[i]);
            int4   tv = __ldcs(&t4[i]);
            acc += bce4(xv, tv);
        }

        __syncthreads();         // publishes slot parity^1; protects slot parity
        parity ^= 1;
        chunk = s_chunk[parity];
    }

    // ---- generic tail for non-covered remainder (empty for 64M inputs) ----
    long long covered = small_base + (long long)(nchunks - nbig) * SMALL_CHUNK;
    for (long long i = covered + (long long)blockIdx.x * blockDim.x + threadIdx.x;
         i < n4; i += (long long)gridDim.x * blockDim.x) {
        acc += bce4(__ldcs(&x4[i]), __ldcs(&t4[i]));
    }

    // ---- block + grid reduction ----
    float bsum = block_reduce(acc, warp_sums);

    __shared__ bool is_last;
    if (threadIdx.x == 0) {
        g_partials[blockIdx.x] = bsum;
        __threadfence();
        unsigned int done = atomicAdd(&g_count, 1u);
        is_last = (done == (unsigned int)(gridDim.x - 1));
    }
    __syncthreads();

    if (is_last) {
        float a2 = 0.0f;
        for (int k = threadIdx.x; k < NBLOCKS; k += NTHREADS)
            a2 += g_partials[k];
        __syncthreads();
        float total = block_reduce(a2, warp_sums);
        if (threadIdx.x == 0) {
            out[0] = total * inv_n;
            g_count = 0;          // reset for next graph replay
            g_work  = 0;
        }
    }
}

extern "C" void kernel_launch(void* const* d_in, const int* in_sizes, int n_in,
                              void* d_out, int out_size)
{
    const float* x = (const float*)d_in[0];
    const int*   t = (const int*)d_in[1];
    float* out = (float*)d_out;

    long long n  = (long long)in_sizes[0];   // 64M
    long long n4 = n >> 2;                   // 16M float4

    // Fine region: last SMALL_CHUNKS * 256 float4 (as much as fits).
    long long small_total = (long long)SMALL_CHUNKS * SMALL_CHUNK;
    if (small_total > n4) small_total = (n4 / SMALL_CHUNK) * SMALL_CHUNK;
    long long bulk = n4 - small_total;
    int  nbig       = (int)(bulk / BIG_CHUNK);
    long long small_base = (long long)nbig * BIG_CHUNK;
    long long small_cover = n4 - small_base;
    int  nsmall     = (int)(small_cover / SMALL_CHUNK);
    int  nchunks    = nbig + nsmall;
    // For 64M: nbig = 15792 (exact), nsmall = 2368, nchunks = 18160, rem 0.

    bce_final8_kernel<<<NBLOCKS, NTHREADS>>>(x, t, out, n4, 1.0f / (float)n,
                                             nbig, nchunks, small_base);
}

// round 15
// speedup vs baseline: 1.0036x; 1.0036x over previous
#include <cuda_runtime.h>
#include <cuda_bf16.h>
#include <cstdint>

// BCE-with-logits mean over 8192x8192, single kernel. FINAL.
// Hot loop = R8 config (best profiled: DRAM 85.4%, ncu 79.9us):
//  - block-level dynamic scheduling, bulk 1024-float4 chunks
//  - fine 256-float4 tail chunks (finish spread ~0.7us)
//  - static first chunk, double-buffered index, one barrier/chunk, __ldcs
// Exit path tuned: acq_rel fences (no sc-fence), float4 partial reduce.
// Counters self-reset (graph-replay safe). Deterministic (no float atomics).

#define NBLOCKS      1184        // 148 SMs * 8 CTAs (one full wave), div by 4
#define NTHREADS     256
#define BIG_IT       4
#define BIG_CHUNK    (NTHREADS * BIG_IT)   // 1024 float4
#define SMALL_CHUNK  NTHREADS              // 256 float4
#define SMALL_CHUNKS 2368                  // 2 * NBLOCKS fine chunks at the end

__device__ __align__(16) float g_partials[NBLOCKS];
__device__ unsigned int g_count = 0;    // always 0 at kernel entry
__device__ unsigned int g_work  = 0;    // always 0 at kernel entry

__device__ __forceinline__ float block_reduce(float acc, float* warp_sums)
{
    #pragma unroll
    for (int off = 16; off > 0; off >>= 1)
        acc += __shfl_down_sync(0xFFFFFFFFu, acc, off);
    int lane = threadIdx.x & 31;
    int wid  = threadIdx.x >> 5;
    if (lane == 0) warp_sums[wid] = acc;
    __syncthreads();
    float v = 0.0f;
    if (wid == 0) {
        v = (lane < NTHREADS / 32) ? warp_sums[lane] : 0.0f;
        #pragma unroll
        for (int off = 16; off > 0; off >>= 1)
            v += __shfl_down_sync(0xFFFFFFFFu, v, off);
    }
    return v;   // valid in warp 0 lane 0
}

__device__ __forceinline__ float bce1(float x, int t)
{
    // t in {0,1}: y = t ? -x : x via sign-bit XOR
    float y = __int_as_float(__float_as_int(x) ^ (t << 31));
    return fmaxf(y, 0.0f) + __logf(1.0f + __expf(-fabsf(y)));
}

__device__ __forceinline__ float bce4(float4 xv, int4 tv)
{
    float s0 = bce1(xv.x, tv.x);
    float s1 = bce1(xv.y, tv.y);
    float s2 = bce1(xv.z, tv.z);
    float s3 = bce1(xv.w, tv.w);
    return (s0 + s1) + (s2 + s3);
}

__global__ __launch_bounds__(NTHREADS) void bce_final9_kernel(
    const float* __restrict__ x, const int* __restrict__ t,
    float* __restrict__ out, long long n4, float inv_n,
    int nbig, int nchunks, long long small_base)
{
    const float4* __restrict__ x4 = (const float4*)x;
    const int4*   __restrict__ t4 = (const int4*)t;

    __shared__ int   s_chunk[2];
    __shared__ float warp_sums[NTHREADS / 32];

    float acc = 0.0f;

    // First chunk is static: no atomic on the startup critical path.
    int parity = 0;
    int chunk  = blockIdx.x;

    while (chunk < nchunks) {
        // prefetch next chunk index into the other slot (hidden under work)
        if (threadIdx.x == 0)
            s_chunk[parity ^ 1] = NBLOCKS + (int)atomicAdd(&g_work, 1u);

        long long base;
        int iters;
        if (chunk < nbig) {
            base  = (long long)chunk * BIG_CHUNK;
            iters = BIG_IT;
        } else {
            base  = small_base + (long long)(chunk - nbig) * SMALL_CHUNK;
            iters = 1;
        }
        base += threadIdx.x;

        #pragma unroll 1
        for (int j = 0; j < iters; j++) {
            long long i = base + (long long)j * NTHREADS;
            float4 xv = __ldcs(&x4[i]);
            int4   tv = __ldcs(&t4[i]);
            acc += bce4(xv, tv);
        }

        __syncthreads();         // publishes slot parity^1; protects slot parity
        parity ^= 1;
        chunk = s_chunk[parity];
    }

    // ---- generic tail for non-covered remainder (empty for 64M inputs) ----
    long long covered = small_base + (long long)(nchunks - nbig) * SMALL_CHUNK;
    for (long long i = covered + (long long)blockIdx.x * blockDim.x + threadIdx.x;
         i < n4; i += (long long)gridDim.x * blockDim.x) {
        acc += bce4(__ldcs(&x4[i]), __ldcs(&t4[i]));
    }

    // ---- block + grid reduction ----
    float bsum = block_reduce(acc, warp_sums);

    __shared__ bool is_last;
    if (threadIdx.x == 0) {
        g_partials[blockIdx.x] = bsum;
        // release: partials visible before the counter increment
        asm volatile("fence.acq_rel.gpu;" ::: "memory");
        unsigned int done = atomicAdd(&g_count, 1u);
        is_last = (done == (unsigned int)(gridDim.x - 1));
    }
    __syncthreads();

    if (is_last) {
        // acquire: counter read above ordered before partials reads below
        asm volatile("fence.acq_rel.gpu;" ::: "memory");
        const float4* p4 = (const float4*)g_partials;
        float a2 = 0.0f;
        for (int k = threadIdx.x; k < NBLOCKS / 4; k += NTHREADS) {
            float4 v = p4[k];
            a2 += (v.x + v.y) + (v.z + v.w);
        }
        __syncthreads();
        float total = block_reduce(a2, warp_sums);
        if (threadIdx.x == 0) {
            out[0] = total * inv_n;
            g_count = 0;          // reset for next graph replay
            g_work  = 0;
        }
    }
}

extern "C" void kernel_launch(void* const* d_in, const int* in_sizes, int n_in,
                              void* d_out, int out_size)
{
    const float* x = (const float*)d_in[0];
    const int*   t = (const int*)d_in[1];
    float* out = (float*)d_out;

    long long n  = (long long)in_sizes[0];   // 64M
    long long n4 = n >> 2;                   // 16M float4

    // Fine region: last SMALL_CHUNKS * 256 float4 (as much as fits).
    long long small_total = (long long)SMALL_CHUNKS * SMALL_CHUNK;
    if (small_total > n4) small_total = (n4 / SMALL_CHUNK) * SMALL_CHUNK;
    long long bulk = n4 - small_total;
    int  nbig       = (int)(bulk / BIG_CHUNK);
    long long small_base = (long long)nbig * BIG_CHUNK;
    long long small_cover = n4 - small_base;
    int  nsmall     = (int)(small_cover / SMALL_CHUNK);
    int  nchunks    = nbig + nsmall;
    // For 64M: nbig = 15792 (exact), nsmall = 2368, nchunks = 18160, rem 0.

    bce_final9_kernel<<<NBLOCKS, NTHREADS>>>(x, t, out, n4, 1.0f / (float)n,
                                             nbig, nchunks, small_base);
}